// round 1
// baseline (speedup 1.0000x reference)
#include <cuda_runtime.h>
#include <cuda_bf16.h>

#define B_ 256
#define N_ 512
#define M_ 1024

// Prescaled logits: logits * log2(e), computed by a preamble kernel each launch.
__device__ float g_lscaled[N_ * M_];

__global__ void prescale_logits_kernel(const float* __restrict__ logits) {
    int i = blockIdx.x * blockDim.x + threadIdx.x;
    if (i < N_ * M_) g_lscaled[i] = logits[i] * 1.4426950408889634f;
}

// Fast exp via exp2: t already in log2 domain.
// Magic-round trick: MAGIC = 2^23 + 2^22 rounds t to nearest integer in the
// mantissa; low bits of the float encoding give the integer, and
// (ni << 23) added to the poly's bits performs an exact ldexp because the
// low 9 bits of 0x4B400000 are zero.
__device__ __forceinline__ float exp2_fast(float t) {
    const float MAGIC = 12582912.0f;  // 2^23 + 2^22
    float tsh = t + MAGIC;
    int   ni  = __float_as_int(tsh);
    float f   = t - (tsh - MAGIC);    // f in [-0.5, 0.5]
    // degree-5 Taylor of 2^f = e^(f ln2), rel err ~2e-6 on the interval
    float p = fmaf(f, 0.0013333558146f, 0.0096181291076f);
    p = fmaf(f, p, 0.055504108664f);
    p = fmaf(f, p, 0.24022650696f);
    p = fmaf(f, p, 0.69314718056f);
    p = fmaf(f, p, 1.0f);
    return __int_as_float(__float_as_int(p) + (ni << 23));
}

__global__ __launch_bounds__(256) void gsm_kernel(
    const float* __restrict__ x,      // [B, M]
    const float* __restrict__ gum,    // [B, N, M]
    float* __restrict__ out)          // [B, N]
{
    const int warp = blockIdx.x * (blockDim.x >> 5) + (threadIdx.x >> 5);
    const int lane = threadIdx.x & 31;
    const int b = warp >> 9;          // / N_
    const int n = warp & (N_ - 1);    // % N_

    const float4* __restrict__ g4 = (const float4*)(gum + (size_t)warp * M_);
    const float4* __restrict__ l4 = (const float4*)(g_lscaled + (size_t)n * M_);
    const float4* __restrict__ x4 = (const float4*)(x + (size_t)b * M_);

    const float L2E = 1.4426950408889634f;
    float s = 0.0f, ws = 0.0f;

    #pragma unroll 4
    for (int it = 0; it < 8; ++it) {
        int idx = it * 32 + lane;     // 128 float4 per row
        float4 gv = g4[idx];
        float4 lv = l4[idx];
        float4 xv = x4[idx];

        float e0 = exp2_fast(fmaf(gv.x, L2E, lv.x));
        float e1 = exp2_fast(fmaf(gv.y, L2E, lv.y));
        float e2 = exp2_fast(fmaf(gv.z, L2E, lv.z));
        float e3 = exp2_fast(fmaf(gv.w, L2E, lv.w));

        s += e0; ws = fmaf(e0, xv.x, ws);
        s += e1; ws = fmaf(e1, xv.y, ws);
        s += e2; ws = fmaf(e2, xv.z, ws);
        s += e3; ws = fmaf(e3, xv.w, ws);
    }

    // warp reduction
    #pragma unroll
    for (int o = 16; o > 0; o >>= 1) {
        s  += __shfl_xor_sync(0xFFFFFFFFu, s, o);
        ws += __shfl_xor_sync(0xFFFFFFFFu, ws, o);
    }

    if (lane == 0) out[warp] = ws / s;
}

extern "C" void kernel_launch(void* const* d_in, const int* in_sizes, int n_in,
                              void* d_out, int out_size) {
    // Identify inputs by element count (all three are distinct):
    //   input  [B, M]    = 262144
    //   logits [N, M]    = 524288
    //   gumbel [B, N, M] = 134217728
    const float* x = nullptr;
    const float* logits = nullptr;
    const float* gum = nullptr;
    for (int i = 0; i < n_in; ++i) {
        if (in_sizes[i] == B_ * M_)       x      = (const float*)d_in[i];
        else if (in_sizes[i] == N_ * M_)  logits = (const float*)d_in[i];
        else                              gum    = (const float*)d_in[i];
    }

    prescale_logits_kernel<<<(N_ * M_ + 255) / 256, 256>>>(logits);

    const int rows = B_ * N_;                 // 131072 warps
    const int warps_per_block = 8;            // 256 threads
    gsm_kernel<<<rows / warps_per_block, 256>>>(x, gum, (float*)d_out);
}